// round 4
// baseline (speedup 1.0000x reference)
#include <cuda_runtime.h>
#include <float.h>

#define BB     16
#define NN     4096
#define SS     1024
#define KK     32
#define CFEAT  64
#define C0     67       // 3 + CFEAT
#define PLANE  524288   // BB*SS*KK
#define EPSV   1e-5f

// ---------------- scratch (device globals; no runtime allocation) ----------
__device__ int    g_fps_idx[BB*SS];
__device__ float  g_new_xyz[BB*SS*3];
__device__ float  g_dcen[BB*SS];
__device__ int    g_knn[BB*SS*KK];
__device__ float  g_z0[(size_t)64 * PLANE];   // [o][b*S*K + s*K + k]
__device__ float  g_z1[(size_t)64 * PLANE];
__device__ float  g_z2[(size_t)128 * PLANE];
__device__ double g_sum0[64],  g_ssq0[64];
__device__ double g_sum1[64],  g_ssq1[64];
__device__ double g_sum2[128], g_ssq2[128];
__device__ float  g_scale0[64],  g_shift0[64];
__device__ float  g_scale1[64],  g_shift1[64];
__device__ float  g_scale2[128], g_shift2[128];
__device__ float  g_dmu, g_dvar;

// ---------------- init: zero stat accumulators -----------------------------
__global__ void init_kernel() {
    int t = threadIdx.x;
    if (t < 64)  { g_sum0[t] = 0.0; g_ssq0[t] = 0.0; g_sum1[t] = 0.0; g_ssq1[t] = 0.0; }
    if (t < 128) { g_sum2[t] = 0.0; g_ssq2[t] = 0.0; }
}

// ---------------- FPS: one block per batch, 512 threads x 8 points ---------
__global__ void fps_kernel(const float* __restrict__ xyz,
                           const float* __restrict__ density,
                           float* __restrict__ out) {
    int b = blockIdx.x;
    int t = threadIdx.x;                      // 512
    const float* Xb = xyz + (size_t)b * NN * 3;

    float px[8], py[8], pz[8], md[8];
#pragma unroll
    for (int i = 0; i < 8; i++) {
        int n = i * 512 + t;
        px[i] = Xb[n*3+0]; py[i] = Xb[n*3+1]; pz[i] = Xb[n*3+2];
        md[i] = 1e10f;
    }

    __shared__ int   s_far;
    __shared__ float swv[16];
    __shared__ int   swi[16];
    if (t == 0) { s_far = 0; g_fps_idx[b*SS] = 0; }
    __syncthreads();

    int lane = t & 31, w = t >> 5;
    for (int it = 0; it < SS; ++it) {
        int far = s_far;
        float qx = Xb[far*3+0], qy = Xb[far*3+1], qz = Xb[far*3+2];
        float bv = -1.f; int bi = NN;
#pragma unroll
        for (int i = 0; i < 8; i++) {
            // exact rounded ops to track reference fp32 (no FMA contraction)
            float dx = __fadd_rn(px[i], -qx);
            float dy = __fadd_rn(py[i], -qy);
            float dz = __fadd_rn(pz[i], -qz);
            float d  = __fadd_rn(__fadd_rn(__fmul_rn(dx,dx), __fmul_rn(dy,dy)),
                                 __fmul_rn(dz,dz));
            float m = fminf(md[i], d);
            md[i] = m;
            int n = i * 512 + t;
            if (m > bv || (m == bv && n < bi)) { bv = m; bi = n; }
        }
        // warp argmax (tie: lowest index)
#pragma unroll
        for (int off = 16; off; off >>= 1) {
            float ov = __shfl_down_sync(0xffffffffu, bv, off);
            int   oi = __shfl_down_sync(0xffffffffu, bi, off);
            if (ov > bv || (ov == bv && oi < bi)) { bv = ov; bi = oi; }
        }
        if (lane == 0) { swv[w] = bv; swi[w] = bi; }
        __syncthreads();
        if (w == 0) {
            float v  = (lane < 16) ? swv[lane] : -1.f;
            int   ix = (lane < 16) ? swi[lane] : NN;
#pragma unroll
            for (int off = 8; off; off >>= 1) {
                float ov = __shfl_down_sync(0xffffffffu, v, off);
                int   oi = __shfl_down_sync(0xffffffffu, ix, off);
                if (ov > v || (ov == v && oi < ix)) { v = ov; ix = oi; }
            }
            if (lane == 0) {
                s_far = ix;
                if (it + 1 < SS) g_fps_idx[b*SS + it + 1] = ix;
            }
        }
        __syncthreads();
    }

    // gather sampled centers + density at centers
    for (int s = t; s < SS; s += 512) {
        int idx = g_fps_idx[b*SS + s];
        float x = Xb[idx*3+0], y = Xb[idx*3+1], z = Xb[idx*3+2];
        int base = (b*SS + s) * 3;
        g_new_xyz[base+0] = x; g_new_xyz[base+1] = y; g_new_xyz[base+2] = z;
        out[base+0] = x; out[base+1] = y; out[base+2] = z;
        g_dcen[b*SS + s] = density[(size_t)b*NN + idx];
    }
}

// ---------------- kNN: one block per query; register-resident selection ----
__global__ void knn_kernel(const float* __restrict__ xyz) {
    int bs = blockIdx.x;                  // 0..16383
    int b  = bs >> 10;
    int t  = threadIdx.x;                 // 256
    const float* Xb = xyz + (size_t)b * NN * 3;

    float qx = g_new_xyz[bs*3+0], qy = g_new_xyz[bs*3+1], qz = g_new_xyz[bs*3+2];
    float qq = __fadd_rn(__fadd_rn(__fmul_rn(qx,qx), __fmul_rn(qy,qy)), __fmul_rn(qz,qz));

    float dl[16];
#pragma unroll
    for (int i = 0; i < 16; i++) {
        int n = i * 256 + t;
        float x = Xb[n*3+0], y = Xb[n*3+1], z = Xb[n*3+2];
        float pp  = __fadd_rn(__fadd_rn(__fmul_rn(x,x), __fmul_rn(y,y)), __fmul_rn(z,z));
        float dot = __fadd_rn(__fadd_rn(__fmul_rn(qx,x), __fmul_rn(qy,y)), __fmul_rn(qz,z));
        dl[i] = __fadd_rn(__fadd_rn(qq, pp), -__fmul_rn(2.f, dot));
    }

    // local min (tie: smaller slot i -> smaller global n)
    float lv = dl[0]; int li = 0;
#pragma unroll
    for (int i = 1; i < 16; i++) if (dl[i] < lv) { lv = dl[i]; li = i; }

    __shared__ float swv[8];
    __shared__ int   swi[8];
    __shared__ int   s_win;
    int lane = t & 31, w = t >> 5;

    for (int r = 0; r < KK; ++r) {
        float v  = lv;
        int   ix = li * 256 + t;
#pragma unroll
        for (int off = 16; off; off >>= 1) {
            float ov = __shfl_down_sync(0xffffffffu, v, off);
            int   oi = __shfl_down_sync(0xffffffffu, ix, off);
            if (ov < v || (ov == v && oi < ix)) { v = ov; ix = oi; }
        }
        if (lane == 0) { swv[w] = v; swi[w] = ix; }
        __syncthreads();
        if (t == 0) {
            float bv = swv[0]; int bi = swi[0];
#pragma unroll
            for (int i = 1; i < 8; i++)
                if (swv[i] < bv || (swv[i] == bv && swi[i] < bi)) { bv = swv[i]; bi = swi[i]; }
            g_knn[bs*KK + r] = bi;
            s_win = bi;
        }
        __syncthreads();
        int win = s_win;
        if ((win & 255) == t) {
#pragma unroll
            for (int i = 0; i < 16; i++) if (i*256 + t == win) dl[i] = FLT_MAX;
            lv = dl[0]; li = 0;
#pragma unroll
            for (int i = 1; i < 16; i++) if (dl[i] < lv) { lv = dl[i]; li = i; }
        }
        __syncthreads();
    }
}

// ---------------- layer 0: gather + 67->64 conv (z0 preactivation) ---------
__global__ void layer0_kernel(const float* __restrict__ xyz,
                              const float* __restrict__ pts,
                              const float* __restrict__ w0,
                              const float* __restrict__ b0) {
    __shared__ __align__(16) float ws[C0*64];      // transposed [c][o]
    __shared__ float bsh[64];
    __shared__ __align__(16) float xin[2][C0][KK];
    __shared__ int   kidx[2][KK];
    __shared__ float ctr[2][3];

    int tid = threadIdx.x;            // 128
    int g   = tid >> 6, gt = tid & 63;
    int q   = blockIdx.x * 2 + g;
    int b   = q >> 10;

    for (int i = tid; i < 64*C0; i += 128) {
        int o = i / C0, c = i % C0;
        ws[c*64 + o] = w0[i];
    }
    if (tid < 64) bsh[tid] = b0[tid];
    if (gt < KK)  kidx[g][gt] = g_knn[q*KK + gt];
    if (gt < 3)   ctr[g][gt]  = g_new_xyz[q*3 + gt];
    __syncthreads();

    const float* Xb = xyz + (size_t)b * NN * 3;
    const float* Pb = pts + (size_t)b * CFEAT * NN;
    for (int j = gt; j < C0*KK; j += 64) {
        int c = j >> 5, k = j & 31;
        int idx = kidx[g][k];
        float v;
        if (c < 3) v = Xb[idx*3 + c] - ctr[g][c];
        else       v = Pb[(size_t)(c-3)*NN + idx];
        xin[g][c][k] = v;
    }
    __syncthreads();

    int ot = gt & 15, kt = gt >> 4;
    int o0 = ot * 4,  k0 = kt * 8;
    float acc[4][8];
#pragma unroll
    for (int i = 0; i < 4; i++) {
        float bb = bsh[o0+i];
#pragma unroll
        for (int j = 0; j < 8; j++) acc[i][j] = bb;
    }
    for (int c = 0; c < C0; c++) {
        float4 wv = *reinterpret_cast<const float4*>(&ws[c*64 + o0]);
        float4 xa = *reinterpret_cast<const float4*>(&xin[g][c][k0]);
        float4 xb = *reinterpret_cast<const float4*>(&xin[g][c][k0+4]);
        float wa[4] = {wv.x, wv.y, wv.z, wv.w};
        float xv[8] = {xa.x, xa.y, xa.z, xa.w, xb.x, xb.y, xb.z, xb.w};
#pragma unroll
        for (int i = 0; i < 4; i++)
#pragma unroll
            for (int j = 0; j < 8; j++)
                acc[i][j] = fmaf(wa[i], xv[j], acc[i][j]);
    }
    size_t base = (size_t)q * KK + k0;
#pragma unroll
    for (int i = 0; i < 4; i++) {
        float4 v0 = make_float4(acc[i][0], acc[i][1], acc[i][2], acc[i][3]);
        float4 v1 = make_float4(acc[i][4], acc[i][5], acc[i][6], acc[i][7]);
        *reinterpret_cast<float4*>(&g_z0[(size_t)(o0+i)*PLANE + base])     = v0;
        *reinterpret_cast<float4*>(&g_z0[(size_t)(o0+i)*PLANE + base + 4]) = v1;
    }
}

// ---------------- layers 1/2: BN+ReLU(zin) then 64->OUT conv ---------------
template<int LAYER>
__global__ void layerN_kernel(const float* __restrict__ w,
                              const float* __restrict__ bias) {
    constexpr int OUT = (LAYER == 1) ? 64 : 128;
    constexpr int QPB = (LAYER == 1) ? 2 : 1;
    constexpr int CIN = 64;
    const float* zin   = (LAYER == 1) ? g_z0 : g_z1;
    float*       zout  = (LAYER == 1) ? g_z1 : g_z2;
    const float* scg   = (LAYER == 1) ? g_scale0 : g_scale1;
    const float* shg   = (LAYER == 1) ? g_shift0 : g_shift1;

    __shared__ __align__(16) float ws[CIN*OUT];        // transposed [c][o]
    __shared__ float bsh[OUT];
    __shared__ __align__(16) float xin[QPB][CIN][KK];
    __shared__ float scs[CIN], shs[CIN];

    int tid = threadIdx.x;            // 128
    int g   = tid / OUT, gt = tid % OUT;
    int q   = blockIdx.x * QPB + g;

    for (int i = tid; i < OUT*CIN; i += 128) {
        int o = i >> 6, c = i & 63;
        ws[c*OUT + o] = w[i];
    }
    if (tid < OUT) bsh[tid] = bias[tid];
    if (tid < CIN) { scs[tid] = scg[tid]; shs[tid] = shg[tid]; }
    __syncthreads();

    for (int j = gt; j < CIN*KK; j += OUT) {
        int c = j >> 5, k = j & 31;
        float v = zin[(size_t)c*PLANE + (size_t)q*KK + k];
        xin[g][c][k] = fmaxf(fmaf(v, scs[c], shs[c]), 0.f);
    }
    __syncthreads();

    constexpr int OT = OUT / 4;
    int ot = gt % OT, kt = gt / OT;
    int o0 = ot * 4,  k0 = kt * 8;
    float acc[4][8];
#pragma unroll
    for (int i = 0; i < 4; i++) {
        float bb = bsh[o0+i];
#pragma unroll
        for (int j = 0; j < 8; j++) acc[i][j] = bb;
    }
#pragma unroll 4
    for (int c = 0; c < CIN; c++) {
        float4 wv = *reinterpret_cast<const float4*>(&ws[c*OUT + o0]);
        float4 xa = *reinterpret_cast<const float4*>(&xin[g][c][k0]);
        float4 xb = *reinterpret_cast<const float4*>(&xin[g][c][k0+4]);
        float wa[4] = {wv.x, wv.y, wv.z, wv.w};
        float xv[8] = {xa.x, xa.y, xa.z, xa.w, xb.x, xb.y, xb.z, xb.w};
#pragma unroll
        for (int i = 0; i < 4; i++)
#pragma unroll
            for (int j = 0; j < 8; j++)
                acc[i][j] = fmaf(wa[i], xv[j], acc[i][j]);
    }
    size_t base = (size_t)q * KK + k0;
#pragma unroll
    for (int i = 0; i < 4; i++) {
        float4 v0 = make_float4(acc[i][0], acc[i][1], acc[i][2], acc[i][3]);
        float4 v1 = make_float4(acc[i][4], acc[i][5], acc[i][6], acc[i][7]);
        *reinterpret_cast<float4*>(&zout[(size_t)(o0+i)*PLANE + base])     = v0;
        *reinterpret_cast<float4*>(&zout[(size_t)(o0+i)*PLANE + base + 4]) = v1;
    }
}

// ---------------- per-channel BN statistics --------------------------------
__global__ void stats_kernel(int which) {
    const float* z; double* sum; double* ssq;
    if (which == 0)      { z = g_z0; sum = g_sum0; ssq = g_ssq0; }
    else if (which == 1) { z = g_z1; sum = g_sum1; ssq = g_ssq1; }
    else                 { z = g_z2; sum = g_sum2; ssq = g_ssq2; }
    int c = blockIdx.x >> 3, part = blockIdx.x & 7;
    size_t base = (size_t)c * PLANE + (size_t)part * 65536;
    double s = 0.0, q = 0.0;
    for (int i = threadIdx.x; i < 65536; i += 256) {
        float v = z[base + i];
        s += (double)v;
        q += (double)v * (double)v;
    }
#pragma unroll
    for (int off = 16; off; off >>= 1) {
        s += __shfl_down_sync(0xffffffffu, s, off);
        q += __shfl_down_sync(0xffffffffu, q, off);
    }
    __shared__ double sw[8], qw[8];
    int w = threadIdx.x >> 5, lane = threadIdx.x & 31;
    if (lane == 0) { sw[w] = s; qw[w] = q; }
    __syncthreads();
    if (threadIdx.x == 0) {
        double S = 0.0, Q = 0.0;
#pragma unroll
        for (int i = 0; i < 8; i++) { S += sw[i]; Q += qw[i]; }
        atomicAdd(&sum[c], S);
        atomicAdd(&ssq[c], Q);
    }
}

__global__ void finalize_kernel(int which, const float* __restrict__ gg,
                                const float* __restrict__ be) {
    const double* sum; const double* ssq; float* scale; float* shift; int C;
    if (which == 0)      { sum = g_sum0; ssq = g_ssq0; scale = g_scale0; shift = g_shift0; C = 64; }
    else if (which == 1) { sum = g_sum1; ssq = g_ssq1; scale = g_scale1; shift = g_shift1; C = 64; }
    else                 { sum = g_sum2; ssq = g_ssq2; scale = g_scale2; shift = g_shift2; C = 128; }
    int c = threadIdx.x;
    if (c >= C) return;
    double mean = sum[c] / (double)PLANE;
    double var  = ssq[c] / (double)PLANE - mean * mean;
    float istd  = rsqrtf((float)var + EPSV);
    float sc    = istd * gg[c];
    scale[c] = sc;
    shift[c] = be[c] - (float)mean * sc;
}

// ---------------- density statistics (mu, var over B*S) --------------------
__global__ void dstats_kernel() {
    double s = 0.0, q = 0.0;
    for (int i = threadIdx.x; i < BB*SS; i += 256) {
        float v = g_dcen[i];
        s += (double)v;
        q += (double)v * (double)v;
    }
#pragma unroll
    for (int off = 16; off; off >>= 1) {
        s += __shfl_down_sync(0xffffffffu, s, off);
        q += __shfl_down_sync(0xffffffffu, q, off);
    }
    __shared__ double sw[8], qw[8];
    int w = threadIdx.x >> 5, lane = threadIdx.x & 31;
    if (lane == 0) { sw[w] = s; qw[w] = q; }
    __syncthreads();
    if (threadIdx.x == 0) {
        double S = 0.0, Q = 0.0;
#pragma unroll
        for (int i = 0; i < 8; i++) { S += sw[i]; Q += qw[i]; }
        double mu = S / (double)(BB*SS);
        g_dmu  = (float)mu;
        g_dvar = (float)(Q / (double)(BB*SS) - mu * mu);
    }
}

// ---------------- final: BN+ReLU(z2), max over k, density weight -----------
__global__ void final_kernel(const float* __restrict__ wd,
                             const float* __restrict__ gd,
                             const float* __restrict__ bed,
                             float* __restrict__ out) {
    int bs = blockIdx.x;          // 16384
    int o  = threadIdx.x;         // 128
    float d   = g_dcen[bs];
    float wdv = wd[o];
    // bn of (wd*d + bd): mean = wd*mu + bd, var = wd^2 * var_d
    float dw = wdv * (d - g_dmu) * rsqrtf(wdv * wdv * g_dvar + EPSV) * gd[o] + bed[o];
    dw = fmaxf(dw, 0.f);

    float sc = g_scale2[o], sh = g_shift2[o];
    size_t base = (size_t)o * PLANE + (size_t)bs * KK;
    float m = -FLT_MAX;
#pragma unroll
    for (int k = 0; k < KK; k += 4) {
        float4 v = *reinterpret_cast<const float4*>(&g_z2[base + k]);
        m = fmaxf(m, fmaf(v.x, sc, sh));
        m = fmaxf(m, fmaf(v.y, sc, sh));
        m = fmaxf(m, fmaf(v.z, sc, sh));
        m = fmaxf(m, fmaf(v.w, sc, sh));
    }
    m = fmaxf(m, 0.f);           // relu then max == clamp(max)
    int b = bs >> 10, s = bs & 1023;
    out[BB*SS*3 + ((size_t)b * 128 + o) * SS + s] = m * dw;
}

// ---------------- launch ----------------------------------------------------
extern "C" void kernel_launch(void* const* d_in, const int* in_sizes, int n_in,
                              void* d_out, int out_size) {
    const float* xyz     = (const float*)d_in[0];
    const float* points  = (const float*)d_in[1];
    const float* density = (const float*)d_in[2];
    const float* w0 = (const float*)d_in[3];
    const float* b0 = (const float*)d_in[4];
    const float* g0 = (const float*)d_in[5];
    const float* be0= (const float*)d_in[6];
    const float* w1 = (const float*)d_in[7];
    const float* b1 = (const float*)d_in[8];
    const float* g1 = (const float*)d_in[9];
    const float* be1= (const float*)d_in[10];
    const float* w2 = (const float*)d_in[11];
    const float* b2 = (const float*)d_in[12];
    const float* g2 = (const float*)d_in[13];
    const float* be2= (const float*)d_in[14];
    const float* wd = (const float*)d_in[15];
    const float* gd = (const float*)d_in[17];
    const float* bed= (const float*)d_in[18];
    float* out = (float*)d_out;

    init_kernel<<<1, 128>>>();
    fps_kernel<<<BB, 512>>>(xyz, density, out);
    dstats_kernel<<<1, 256>>>();
    knn_kernel<<<BB*SS, 256>>>(xyz);
    layer0_kernel<<<BB*SS/2, 128>>>(xyz, points, w0, b0);
    stats_kernel<<<64*8, 256>>>(0);
    finalize_kernel<<<1, 128>>>(0, g0, be0);
    layerN_kernel<1><<<BB*SS/2, 128>>>(w1, b1);
    stats_kernel<<<64*8, 256>>>(1);
    finalize_kernel<<<1, 128>>>(1, g1, be1);
    layerN_kernel<2><<<BB*SS, 128>>>(w2, b2);
    stats_kernel<<<128*8, 256>>>(2);
    finalize_kernel<<<1, 128>>>(2, g2, be2);
    final_kernel<<<BB*SS, 128>>>(wd, gd, bed, out);
}

// round 5
// speedup vs baseline: 1.0020x; 1.0020x over previous
#include <cuda_runtime.h>
#include <float.h>

#define BB     16
#define NN     4096
#define SS     1024
#define KK     32
#define CFEAT  64
#define C0     67       // 3 + CFEAT
#define PLANE  524288   // BB*SS*KK
#define EPSV   1e-5f

// ---------------- scratch (device globals; no runtime allocation) ----------
__device__ int    g_fps_idx[BB*SS];
__device__ float  g_new_xyz[BB*SS*3];
__device__ float  g_dcen[BB*SS];
__device__ int    g_knn[BB*SS*KK];
__device__ float  g_z0[(size_t)64 * PLANE];   // [o][b*S*K + s*K + k]
__device__ float  g_z1[(size_t)64 * PLANE];
__device__ float  g_z2[(size_t)128 * PLANE];
__device__ double g_sum0[64],  g_ssq0[64];
__device__ double g_sum1[64],  g_ssq1[64];
__device__ double g_sum2[128], g_ssq2[128];
__device__ float  g_scale0[64],  g_shift0[64];
__device__ float  g_scale1[64],  g_shift1[64];
__device__ float  g_scale2[128], g_shift2[128];
__device__ float  g_dmu, g_dvar;

// ---------------- init: zero stat accumulators -----------------------------
__global__ void init_kernel() {
    int t = threadIdx.x;
    if (t < 64)  { g_sum0[t] = 0.0; g_ssq0[t] = 0.0; g_sum1[t] = 0.0; g_ssq1[t] = 0.0; }
    if (t < 128) { g_sum2[t] = 0.0; g_ssq2[t] = 0.0; }
}

// ---------------- FPS: one block per batch, 512 threads x 8 points ---------
__global__ void fps_kernel(const float* __restrict__ xyz,
                           const float* __restrict__ density,
                           float* __restrict__ out) {
    int b = blockIdx.x;
    int t = threadIdx.x;                      // 512
    const float* Xb = xyz + (size_t)b * NN * 3;

    float px[8], py[8], pz[8], md[8];
#pragma unroll
    for (int i = 0; i < 8; i++) {
        int n = i * 512 + t;
        px[i] = Xb[n*3+0]; py[i] = Xb[n*3+1]; pz[i] = Xb[n*3+2];
        md[i] = 1e10f;
    }

    __shared__ int   s_far;
    __shared__ float swv[16];
    __shared__ int   swi[16];
    if (t == 0) { s_far = 0; g_fps_idx[b*SS] = 0; }
    __syncthreads();

    int lane = t & 31, w = t >> 5;
    for (int it = 0; it < SS; ++it) {
        int far = s_far;
        float qx = Xb[far*3+0], qy = Xb[far*3+1], qz = Xb[far*3+2];
        float bv = -1.f; int bi = NN;
#pragma unroll
        for (int i = 0; i < 8; i++) {
            // exact rounded ops to track reference fp32 (no FMA contraction)
            float dx = __fadd_rn(px[i], -qx);
            float dy = __fadd_rn(py[i], -qy);
            float dz = __fadd_rn(pz[i], -qz);
            float d  = __fadd_rn(__fadd_rn(__fmul_rn(dx,dx), __fmul_rn(dy,dy)),
                                 __fmul_rn(dz,dz));
            float m = fminf(md[i], d);
            md[i] = m;
            int n = i * 512 + t;
            if (m > bv || (m == bv && n < bi)) { bv = m; bi = n; }
        }
        // warp argmax (tie: lowest index)
#pragma unroll
        for (int off = 16; off; off >>= 1) {
            float ov = __shfl_down_sync(0xffffffffu, bv, off);
            int   oi = __shfl_down_sync(0xffffffffu, bi, off);
            if (ov > bv || (ov == bv && oi < bi)) { bv = ov; bi = oi; }
        }
        if (lane == 0) { swv[w] = bv; swi[w] = bi; }
        __syncthreads();
        if (w == 0) {
            float v  = (lane < 16) ? swv[lane] : -1.f;
            int   ix = (lane < 16) ? swi[lane] : NN;
#pragma unroll
            for (int off = 8; off; off >>= 1) {
                float ov = __shfl_down_sync(0xffffffffu, v, off);
                int   oi = __shfl_down_sync(0xffffffffu, ix, off);
                if (ov > v || (ov == v && oi < ix)) { v = ov; ix = oi; }
            }
            if (lane == 0) {
                s_far = ix;
                if (it + 1 < SS) g_fps_idx[b*SS + it + 1] = ix;
            }
        }
        __syncthreads();
    }

    // gather sampled centers + density at centers
    for (int s = t; s < SS; s += 512) {
        int idx = g_fps_idx[b*SS + s];
        float x = Xb[idx*3+0], y = Xb[idx*3+1], z = Xb[idx*3+2];
        int base = (b*SS + s) * 3;
        g_new_xyz[base+0] = x; g_new_xyz[base+1] = y; g_new_xyz[base+2] = z;
        out[base+0] = x; out[base+1] = y; out[base+2] = z;
        g_dcen[b*SS + s] = density[(size_t)b*NN + idx];
    }
}

// ---------------- kNN: one block per query; register-resident selection ----
__global__ void knn_kernel(const float* __restrict__ xyz) {
    int bs = blockIdx.x;                  // 0..16383
    int b  = bs >> 10;
    int t  = threadIdx.x;                 // 256
    const float* Xb = xyz + (size_t)b * NN * 3;

    float qx = g_new_xyz[bs*3+0], qy = g_new_xyz[bs*3+1], qz = g_new_xyz[bs*3+2];
    float qq = __fadd_rn(__fadd_rn(__fmul_rn(qx,qx), __fmul_rn(qy,qy)), __fmul_rn(qz,qz));

    float dl[16];
#pragma unroll
    for (int i = 0; i < 16; i++) {
        int n = i * 256 + t;
        float x = Xb[n*3+0], y = Xb[n*3+1], z = Xb[n*3+2];
        float pp  = __fadd_rn(__fadd_rn(__fmul_rn(x,x), __fmul_rn(y,y)), __fmul_rn(z,z));
        float dot = __fadd_rn(__fadd_rn(__fmul_rn(qx,x), __fmul_rn(qy,y)), __fmul_rn(qz,z));
        dl[i] = __fadd_rn(__fadd_rn(qq, pp), -__fmul_rn(2.f, dot));
    }

    // local min (tie: smaller slot i -> smaller global n)
    float lv = dl[0]; int li = 0;
#pragma unroll
    for (int i = 1; i < 16; i++) if (dl[i] < lv) { lv = dl[i]; li = i; }

    __shared__ float swv[8];
    __shared__ int   swi[8];
    __shared__ int   s_win;
    int lane = t & 31, w = t >> 5;

    for (int r = 0; r < KK; ++r) {
        float v  = lv;
        int   ix = li * 256 + t;
#pragma unroll
        for (int off = 16; off; off >>= 1) {
            float ov = __shfl_down_sync(0xffffffffu, v, off);
            int   oi = __shfl_down_sync(0xffffffffu, ix, off);
            if (ov < v || (ov == v && oi < ix)) { v = ov; ix = oi; }
        }
        if (lane == 0) { swv[w] = v; swi[w] = ix; }
        __syncthreads();
        if (t == 0) {
            float bv = swv[0]; int bi = swi[0];
#pragma unroll
            for (int i = 1; i < 8; i++)
                if (swv[i] < bv || (swv[i] == bv && swi[i] < bi)) { bv = swv[i]; bi = swi[i]; }
            g_knn[bs*KK + r] = bi;
            s_win = bi;
        }
        __syncthreads();
        int win = s_win;
        if ((win & 255) == t) {
#pragma unroll
            for (int i = 0; i < 16; i++) if (i*256 + t == win) dl[i] = FLT_MAX;
            lv = dl[0]; li = 0;
#pragma unroll
            for (int i = 1; i < 16; i++) if (dl[i] < lv) { lv = dl[i]; li = i; }
        }
        __syncthreads();
    }
}

// ---------------- layer 0: gather + 67->64 conv (z0 preactivation) ---------
__global__ void layer0_kernel(const float* __restrict__ xyz,
                              const float* __restrict__ pts,
                              const float* __restrict__ w0,
                              const float* __restrict__ b0) {
    __shared__ __align__(16) float ws[C0*64];      // transposed [c][o]
    __shared__ float bsh[64];
    __shared__ __align__(16) float xin[2][C0][KK];
    __shared__ int   kidx[2][KK];
    __shared__ float ctr[2][3];

    int tid = threadIdx.x;            // 128
    int g   = tid >> 6, gt = tid & 63;
    int q   = blockIdx.x * 2 + g;
    int b   = q >> 10;

    for (int i = tid; i < 64*C0; i += 128) {
        int o = i / C0, c = i % C0;
        ws[c*64 + o] = w0[i];
    }
    if (tid < 64) bsh[tid] = b0[tid];
    if (gt < KK)  kidx[g][gt] = g_knn[q*KK + gt];
    if (gt < 3)   ctr[g][gt]  = g_new_xyz[q*3 + gt];
    __syncthreads();

    const float* Xb = xyz + (size_t)b * NN * 3;
    const float* Pb = pts + (size_t)b * CFEAT * NN;
    for (int j = gt; j < C0*KK; j += 64) {
        int c = j >> 5, k = j & 31;
        int idx = kidx[g][k];
        float v;
        if (c < 3) v = Xb[idx*3 + c] - ctr[g][c];
        else       v = Pb[(size_t)(c-3)*NN + idx];
        xin[g][c][k] = v;
    }
    __syncthreads();

    int ot = gt & 15, kt = gt >> 4;
    int o0 = ot * 4,  k0 = kt * 8;
    float acc[4][8];
#pragma unroll
    for (int i = 0; i < 4; i++) {
        float bb = bsh[o0+i];
#pragma unroll
        for (int j = 0; j < 8; j++) acc[i][j] = bb;
    }
    for (int c = 0; c < C0; c++) {
        float4 wv = *reinterpret_cast<const float4*>(&ws[c*64 + o0]);
        float4 xa = *reinterpret_cast<const float4*>(&xin[g][c][k0]);
        float4 xb = *reinterpret_cast<const float4*>(&xin[g][c][k0+4]);
        float wa[4] = {wv.x, wv.y, wv.z, wv.w};
        float xv[8] = {xa.x, xa.y, xa.z, xa.w, xb.x, xb.y, xb.z, xb.w};
#pragma unroll
        for (int i = 0; i < 4; i++)
#pragma unroll
            for (int j = 0; j < 8; j++)
                acc[i][j] = fmaf(wa[i], xv[j], acc[i][j]);
    }
    size_t base = (size_t)q * KK + k0;
#pragma unroll
    for (int i = 0; i < 4; i++) {
        float4 v0 = make_float4(acc[i][0], acc[i][1], acc[i][2], acc[i][3]);
        float4 v1 = make_float4(acc[i][4], acc[i][5], acc[i][6], acc[i][7]);
        *reinterpret_cast<float4*>(&g_z0[(size_t)(o0+i)*PLANE + base])     = v0;
        *reinterpret_cast<float4*>(&g_z0[(size_t)(o0+i)*PLANE + base + 4]) = v1;
    }
}

// ---------------- layers 1/2: BN+ReLU(zin) then 64->OUT conv ---------------
template<int LAYER>
__global__ void layerN_kernel(const float* __restrict__ w,
                              const float* __restrict__ bias) {
    constexpr int OUT = (LAYER == 1) ? 64 : 128;
    constexpr int QPB = (LAYER == 1) ? 2 : 1;
    constexpr int CIN = 64;
    const float* zin   = (LAYER == 1) ? g_z0 : g_z1;
    float*       zout  = (LAYER == 1) ? g_z1 : g_z2;
    const float* scg   = (LAYER == 1) ? g_scale0 : g_scale1;
    const float* shg   = (LAYER == 1) ? g_shift0 : g_shift1;

    __shared__ __align__(16) float ws[CIN*OUT];        // transposed [c][o]
    __shared__ float bsh[OUT];
    __shared__ __align__(16) float xin[QPB][CIN][KK];
    __shared__ float scs[CIN], shs[CIN];

    int tid = threadIdx.x;            // 128
    int g   = tid / OUT, gt = tid % OUT;
    int q   = blockIdx.x * QPB + g;

    for (int i = tid; i < OUT*CIN; i += 128) {
        int o = i >> 6, c = i & 63;
        ws[c*OUT + o] = w[i];
    }
    if (tid < OUT) bsh[tid] = bias[tid];
    if (tid < CIN) { scs[tid] = scg[tid]; shs[tid] = shg[tid]; }
    __syncthreads();

    for (int j = gt; j < CIN*KK; j += OUT) {
        int c = j >> 5, k = j & 31;
        float v = zin[(size_t)c*PLANE + (size_t)q*KK + k];
        xin[g][c][k] = fmaxf(fmaf(v, scs[c], shs[c]), 0.f);
    }
    __syncthreads();

    constexpr int OT = OUT / 4;
    int ot = gt % OT, kt = gt / OT;
    int o0 = ot * 4,  k0 = kt * 8;
    float acc[4][8];
#pragma unroll
    for (int i = 0; i < 4; i++) {
        float bb = bsh[o0+i];
#pragma unroll
        for (int j = 0; j < 8; j++) acc[i][j] = bb;
    }
#pragma unroll 4
    for (int c = 0; c < CIN; c++) {
        float4 wv = *reinterpret_cast<const float4*>(&ws[c*OUT + o0]);
        float4 xa = *reinterpret_cast<const float4*>(&xin[g][c][k0]);
        float4 xb = *reinterpret_cast<const float4*>(&xin[g][c][k0+4]);
        float wa[4] = {wv.x, wv.y, wv.z, wv.w};
        float xv[8] = {xa.x, xa.y, xa.z, xa.w, xb.x, xb.y, xb.z, xb.w};
#pragma unroll
        for (int i = 0; i < 4; i++)
#pragma unroll
            for (int j = 0; j < 8; j++)
                acc[i][j] = fmaf(wa[i], xv[j], acc[i][j]);
    }
    size_t base = (size_t)q * KK + k0;
#pragma unroll
    for (int i = 0; i < 4; i++) {
        float4 v0 = make_float4(acc[i][0], acc[i][1], acc[i][2], acc[i][3]);
        float4 v1 = make_float4(acc[i][4], acc[i][5], acc[i][6], acc[i][7]);
        *reinterpret_cast<float4*>(&zout[(size_t)(o0+i)*PLANE + base])     = v0;
        *reinterpret_cast<float4*>(&zout[(size_t)(o0+i)*PLANE + base + 4]) = v1;
    }
}

// ---------------- per-channel BN statistics --------------------------------
__global__ void stats_kernel(int which) {
    const float* z; double* sum; double* ssq;
    if (which == 0)      { z = g_z0; sum = g_sum0; ssq = g_ssq0; }
    else if (which == 1) { z = g_z1; sum = g_sum1; ssq = g_ssq1; }
    else                 { z = g_z2; sum = g_sum2; ssq = g_ssq2; }
    int c = blockIdx.x >> 3, part = blockIdx.x & 7;
    size_t base = (size_t)c * PLANE + (size_t)part * 65536;
    double s = 0.0, q = 0.0;
    for (int i = threadIdx.x; i < 65536; i += 256) {
        float v = z[base + i];
        s += (double)v;
        q += (double)v * (double)v;
    }
#pragma unroll
    for (int off = 16; off; off >>= 1) {
        s += __shfl_down_sync(0xffffffffu, s, off);
        q += __shfl_down_sync(0xffffffffu, q, off);
    }
    __shared__ double sw[8], qw[8];
    int w = threadIdx.x >> 5, lane = threadIdx.x & 31;
    if (lane == 0) { sw[w] = s; qw[w] = q; }
    __syncthreads();
    if (threadIdx.x == 0) {
        double S = 0.0, Q = 0.0;
#pragma unroll
        for (int i = 0; i < 8; i++) { S += sw[i]; Q += qw[i]; }
        atomicAdd(&sum[c], S);
        atomicAdd(&ssq[c], Q);
    }
}

__global__ void finalize_kernel(int which, const float* __restrict__ gg,
                                const float* __restrict__ be) {
    const double* sum; const double* ssq; float* scale; float* shift; int C;
    if (which == 0)      { sum = g_sum0; ssq = g_ssq0; scale = g_scale0; shift = g_shift0; C = 64; }
    else if (which == 1) { sum = g_sum1; ssq = g_ssq1; scale = g_scale1; shift = g_shift1; C = 64; }
    else                 { sum = g_sum2; ssq = g_ssq2; scale = g_scale2; shift = g_shift2; C = 128; }
    int c = threadIdx.x;
    if (c >= C) return;
    double mean = sum[c] / (double)PLANE;
    double var  = ssq[c] / (double)PLANE - mean * mean;
    float istd  = rsqrtf((float)var + EPSV);
    float sc    = istd * gg[c];
    scale[c] = sc;
    shift[c] = be[c] - (float)mean * sc;
}

// ---------------- density statistics (mu, var over B*S) --------------------
__global__ void dstats_kernel() {
    double s = 0.0, q = 0.0;
    for (int i = threadIdx.x; i < BB*SS; i += 256) {
        float v = g_dcen[i];
        s += (double)v;
        q += (double)v * (double)v;
    }
#pragma unroll
    for (int off = 16; off; off >>= 1) {
        s += __shfl_down_sync(0xffffffffu, s, off);
        q += __shfl_down_sync(0xffffffffu, q, off);
    }
    __shared__ double sw[8], qw[8];
    int w = threadIdx.x >> 5, lane = threadIdx.x & 31;
    if (lane == 0) { sw[w] = s; qw[w] = q; }
    __syncthreads();
    if (threadIdx.x == 0) {
        double S = 0.0, Q = 0.0;
#pragma unroll
        for (int i = 0; i < 8; i++) { S += sw[i]; Q += qw[i]; }
        double mu = S / (double)(BB*SS);
        g_dmu  = (float)mu;
        g_dvar = (float)(Q / (double)(BB*SS) - mu * mu);
    }
}

// ---------------- final: BN+ReLU(z2), max over k, density weight -----------
__global__ void final_kernel(const float* __restrict__ wd,
                             const float* __restrict__ gd,
                             const float* __restrict__ bed,
                             float* __restrict__ out) {
    int bs = blockIdx.x;          // 16384
    int o  = threadIdx.x;         // 128
    float d   = g_dcen[bs];
    float wdv = wd[o];
    // bn of (wd*d + bd): mean = wd*mu + bd, var = wd^2 * var_d
    float dw = wdv * (d - g_dmu) * rsqrtf(wdv * wdv * g_dvar + EPSV) * gd[o] + bed[o];
    dw = fmaxf(dw, 0.f);

    float sc = g_scale2[o], sh = g_shift2[o];
    size_t base = (size_t)o * PLANE + (size_t)bs * KK;
    float m = -FLT_MAX;
#pragma unroll
    for (int k = 0; k < KK; k += 4) {
        float4 v = *reinterpret_cast<const float4*>(&g_z2[base + k]);
        m = fmaxf(m, fmaf(v.x, sc, sh));
        m = fmaxf(m, fmaf(v.y, sc, sh));
        m = fmaxf(m, fmaf(v.z, sc, sh));
        m = fmaxf(m, fmaf(v.w, sc, sh));
    }
    m = fmaxf(m, 0.f);           // relu then max == clamp(max)
    int b = bs >> 10, s = bs & 1023;
    out[BB*SS*3 + ((size_t)b * 128 + o) * SS + s] = m * dw;
}

// ---------------- launch ----------------------------------------------------
extern "C" void kernel_launch(void* const* d_in, const int* in_sizes, int n_in,
                              void* d_out, int out_size) {
    const float* xyz     = (const float*)d_in[0];
    const float* points  = (const float*)d_in[1];
    const float* density = (const float*)d_in[2];
    const float* w0 = (const float*)d_in[3];
    const float* b0 = (const float*)d_in[4];
    const float* g0 = (const float*)d_in[5];
    const float* be0= (const float*)d_in[6];
    const float* w1 = (const float*)d_in[7];
    const float* b1 = (const float*)d_in[8];
    const float* g1 = (const float*)d_in[9];
    const float* be1= (const float*)d_in[10];
    const float* w2 = (const float*)d_in[11];
    const float* b2 = (const float*)d_in[12];
    const float* g2 = (const float*)d_in[13];
    const float* be2= (const float*)d_in[14];
    const float* wd = (const float*)d_in[15];
    const float* gd = (const float*)d_in[17];
    const float* bed= (const float*)d_in[18];
    float* out = (float*)d_out;

    init_kernel<<<1, 128>>>();
    fps_kernel<<<BB, 512>>>(xyz, density, out);
    dstats_kernel<<<1, 256>>>();
    knn_kernel<<<BB*SS, 256>>>(xyz);
    layer0_kernel<<<BB*SS/2, 128>>>(xyz, points, w0, b0);
    stats_kernel<<<64*8, 256>>>(0);
    finalize_kernel<<<1, 128>>>(0, g0, be0);
    layerN_kernel<1><<<BB*SS/2, 128>>>(w1, b1);
    stats_kernel<<<64*8, 256>>>(1);
    finalize_kernel<<<1, 128>>>(1, g1, be1);
    layerN_kernel<2><<<BB*SS, 128>>>(w2, b2);
    stats_kernel<<<128*8, 256>>>(2);
    finalize_kernel<<<1, 128>>>(2, g2, be2);
    final_kernel<<<BB*SS, 128>>>(wd, gd, bed, out);
}